// round 1
// baseline (speedup 1.0000x reference)
#include <cuda_runtime.h>
#include <cuda_bf16.h>
#include <math.h>

// Problem constants
#define BB  2
#define SS  2048
#define DD  2048
#define HH  16
#define HDD 128
#define EE  4
#define II  2048
#define TT  (BB*SS)   // 4096 tokens

// ---------------- scratch (device globals; no allocation allowed) ----------------
__device__ float g_xn  [TT*DD];   // layernorm output (reused ln1/ln2)
__device__ float g_q   [TT*DD];
__device__ float g_k   [TT*DD];
__device__ float g_v   [TT*DD];
__device__ float g_attn[TT*DD];
__device__ float g_h   [TT*DD];   // residual after attention
__device__ float g_hmid[TT*II];   // expert fc1 output (reused per expert)
__device__ int   g_cnt [EE];
__device__ int   g_tok [EE*TT];
__device__ float g_w   [EE*TT];

// ---------------- tiny kernels ----------------
__global__ void zero_cnt_kernel() {
    if (threadIdx.x < EE) g_cnt[threadIdx.x] = 0;
}

__global__ void copy_kernel(const float4* __restrict__ src, float4* __restrict__ dst, int n4) {
    int i = blockIdx.x * blockDim.x + threadIdx.x;
    if (i < n4) dst[i] = src[i];
}

// ---------------- LayerNorm: one block per row, 256 threads ----------------
__global__ __launch_bounds__(256) void layernorm_kernel(
    const float* __restrict__ x, const float* __restrict__ w,
    const float* __restrict__ b, float* __restrict__ out)
{
    int row = blockIdx.x;
    const float* xr = x + (size_t)row * DD;
    int t = threadIdx.x;
    float v[8];
    float s = 0.f;
#pragma unroll
    for (int i = 0; i < 8; i++) { v[i] = xr[t + i*256]; s += v[i]; }
    __shared__ float red[256];
    red[t] = s; __syncthreads();
    for (int st = 128; st > 0; st >>= 1) {
        if (t < st) red[t] += red[t + st];
        __syncthreads();
    }
    float mu = red[0] * (1.f / DD);
    __syncthreads();
    float s2 = 0.f;
#pragma unroll
    for (int i = 0; i < 8; i++) { float dv = v[i] - mu; s2 += dv * dv; }
    red[t] = s2; __syncthreads();
    for (int st = 128; st > 0; st >>= 1) {
        if (t < st) red[t] += red[t + st];
        __syncthreads();
    }
    float rstd = rsqrtf(red[0] * (1.f / DD) + 1e-5f);
    float* orow = out + (size_t)row * DD;
#pragma unroll
    for (int i = 0; i < 8; i++) {
        int d = t + i*256;
        orow[d] = (v[i] - mu) * rstd * w[d] + b[d];
    }
}

// ---------------- RoPE in-place on Q and K ----------------
__global__ void rope_kernel(float* __restrict__ Q, float* __restrict__ K) {
    int i = blockIdx.x * blockDim.x + threadIdx.x;   // < T*H*64
    if (i >= TT * HH * 64) return;
    int di   = i & 63;
    int rest = i >> 6;
    int h    = rest & (HH - 1);
    int bs   = rest >> 4;
    int pos  = bs & (SS - 1);
    // inv_freq = 10000^(-di/64) = exp(-di * ln(10000)/64)
    float invf = expf(-(float)di * 0.14391156516685623f);
    float ang  = (float)pos * invf;
    float sn, c;
    sincosf(ang, &sn, &c);
    size_t base = (size_t)bs * DD + h * HDD + di;
    float q1 = Q[base], q2 = Q[base + 64];
    Q[base]      = q1 * c - q2 * sn;
    Q[base + 64] = q2 * c + q1 * sn;
    float k1 = K[base], k2 = K[base + 64];
    K[base]      = k1 * c - k2 * sn;
    K[base + 64] = k2 * c + k1 * sn;
}

// ---------------- causal flash attention, fp32 ----------------
// grid: (S/64, B*H); block: 128 threads; 2 threads per q-row (64-dim halves)
#define KPAD 132
__global__ __launch_bounds__(128) void flash_kernel(
    const float* __restrict__ Q, const float* __restrict__ K,
    const float* __restrict__ V, float* __restrict__ O)
{
    __shared__ float Ks[32][KPAD];
    __shared__ float Vs[32][KPAD];
    int bh = blockIdx.y;
    int b = bh >> 4, h = bh & 15;
    int q0 = blockIdx.x * 64;
    int t = threadIdx.x;
    int r = t >> 1, half = t & 1;
    int qg = q0 + r;
    size_t qoff = ((size_t)(b * SS + qg)) * DD + h * HDD + half * 64;
    float qreg[64];
#pragma unroll
    for (int d = 0; d < 64; d++) qreg[d] = Q[qoff + d];
    float acc[64];
#pragma unroll
    for (int d = 0; d < 64; d++) acc[d] = 0.f;
    float mval = -1e30f, l = 0.f;
    int nk = q0 + 64;                      // causal: keys 0..q0+63
    int hb = half * 68;                    // padded half offset (bank-shifted)
    for (int j0 = 0; j0 < nk; j0 += 32) {
#pragma unroll
        for (int i = 0; i < 8; i++) {
            int idx = t + i * 128;         // 0..1023 float4 slots
            int row = idx >> 5;
            int c4  = idx & 31;
            int co  = c4 * 4 + (c4 >= 16 ? 4 : 0);
            size_t g = ((size_t)(b * SS + j0 + row)) * DD + h * HDD + c4 * 4;
            *(float4*)&Ks[row][co] = *(const float4*)(K + g);
            *(float4*)&Vs[row][co] = *(const float4*)(V + g);
        }
        __syncthreads();
        float s[32];
#pragma unroll
        for (int j = 0; j < 32; j++) {
            float p = 0.f;
#pragma unroll
            for (int d = 0; d < 64; d++) p += qreg[d] * Ks[j][hb + d];
            p += __shfl_xor_sync(0xffffffffu, p, 1);
            float sc = p * 0.08838834764831845f;   // 1/sqrt(128)
            if (j0 + j > qg) sc = -1e30f;
            s[j] = sc;
        }
        float tmax = -1e30f;
#pragma unroll
        for (int j = 0; j < 32; j++) tmax = fmaxf(tmax, s[j]);
        float mnew = fmaxf(mval, tmax);
        float scale = __expf(mval - mnew);
        l *= scale;
#pragma unroll
        for (int d = 0; d < 64; d++) acc[d] *= scale;
#pragma unroll
        for (int j = 0; j < 32; j++) {
            float p = __expf(s[j] - mnew);
            l += p;
#pragma unroll
            for (int d = 0; d < 64; d++) acc[d] += p * Vs[j][hb + d];
        }
        mval = mnew;
        __syncthreads();
    }
    float inv = 1.f / l;
#pragma unroll
    for (int d = 0; d < 64; d++) O[qoff + d] = acc[d] * inv;
}

// ---------------- generic SGEMM 128x128x16, 256 threads, 8x8 microtile ----------------
// MODE 0: C = acc + bias
// MODE 1: C = acc + bias + res
// MODE 2: C = gelu(acc + bias)          (exact GELU, used with GATHER for expert fc1)
// MODE 3: C[scatterIdx[m]] += w[m]*(acc + bias)   (expert fc2 scatter-accumulate)
__device__ __forceinline__ float gelu_exact(float x) {
    return 0.5f * x * (1.0f + erff(x * 0.70710678118654752f));
}

template<int MODE, bool GATHER>
__global__ __launch_bounds__(256) void sgemm_kernel(
    const float* __restrict__ A, const float* __restrict__ B, const float* __restrict__ bias,
    float* __restrict__ C, const float* __restrict__ res,
    const int* __restrict__ gatherIdx, const int* __restrict__ cntPtr,
    const int* __restrict__ scatterIdx, const float* __restrict__ scatterW,
    int M, int N, int K)
{
    int Meff = cntPtr ? *cntPtr : M;
    int rowBase = blockIdx.y * 128;
    if (rowBase >= Meff) return;
    int colBase = blockIdx.x * 128;

    __shared__ float As[16][128];
    __shared__ float Bs[16][128];

    int tid = threadIdx.x;
    int tx = tid & 15, ty = tid >> 4;

    float acc[8][8];
#pragma unroll
    for (int i = 0; i < 8; i++)
#pragma unroll
        for (int j = 0; j < 8; j++) acc[i][j] = 0.f;

    // A-tile load mapping: 512 float4 (128 rows x 4 float4), 2 per thread
    int aidx0 = tid * 2, aidx1 = tid * 2 + 1;
    int ar0 = aidx0 >> 2, ak0 = (aidx0 & 3) * 4;
    int ar1 = aidx1 >> 2, ak1 = (aidx1 & 3) * 4;
    int gm0 = rowBase + ar0, gm1 = rowBase + ar1;
    bool v0 = gm0 < Meff, v1 = gm1 < Meff;
    const float* Ap0 = nullptr; const float* Ap1 = nullptr;
    if (v0) { size_t rr = GATHER ? (size_t)gatherIdx[gm0] : (size_t)gm0; Ap0 = A + rr * (size_t)K; }
    if (v1) { size_t rr = GATHER ? (size_t)gatherIdx[gm1] : (size_t)gm1; Ap1 = A + rr * (size_t)K; }
    // B-tile load mapping: 512 float4 (16 rows x 32 float4)
    int br0 = aidx0 >> 5, bc0 = (aidx0 & 31) * 4;
    int br1 = aidx1 >> 5, bc1 = (aidx1 & 31) * 4;

    for (int k0 = 0; k0 < K; k0 += 16) {
        float4 a0 = make_float4(0.f,0.f,0.f,0.f), a1 = a0;
        if (v0) a0 = *(const float4*)(Ap0 + k0 + ak0);
        if (v1) a1 = *(const float4*)(Ap1 + k0 + ak1);
        As[ak0+0][ar0] = a0.x; As[ak0+1][ar0] = a0.y; As[ak0+2][ar0] = a0.z; As[ak0+3][ar0] = a0.w;
        As[ak1+0][ar1] = a1.x; As[ak1+1][ar1] = a1.y; As[ak1+2][ar1] = a1.z; As[ak1+3][ar1] = a1.w;
        *(float4*)&Bs[br0][bc0] = *(const float4*)(B + (size_t)(k0 + br0) * N + colBase + bc0);
        *(float4*)&Bs[br1][bc1] = *(const float4*)(B + (size_t)(k0 + br1) * N + colBase + bc1);
        __syncthreads();
#pragma unroll
        for (int kk = 0; kk < 16; kk++) {
            float a[8], b[8];
            *(float4*)&a[0] = *(const float4*)&As[kk][ty*8];
            *(float4*)&a[4] = *(const float4*)&As[kk][ty*8+4];
            *(float4*)&b[0] = *(const float4*)&Bs[kk][tx*8];
            *(float4*)&b[4] = *(const float4*)&Bs[kk][tx*8+4];
#pragma unroll
            for (int i = 0; i < 8; i++)
#pragma unroll
                for (int j = 0; j < 8; j++) acc[i][j] += a[i] * b[j];
        }
        __syncthreads();
    }

    float bv[8];
#pragma unroll
    for (int j = 0; j < 8; j++) bv[j] = bias[colBase + tx*8 + j];

#pragma unroll
    for (int i = 0; i < 8; i++) {
        int m = rowBase + ty*8 + i;
        if (m >= Meff) continue;
        if (MODE == 3) {
            int trow = scatterIdx[m];
            float wgt = scatterW[m];
            float* crow = C + (size_t)trow * N + colBase + tx*8;
#pragma unroll
            for (int j = 0; j < 8; j++)
                crow[j] += wgt * (acc[i][j] + bv[j]);
        } else {
            float* crow = C + (size_t)m * N + colBase + tx*8;
#pragma unroll
            for (int j = 0; j < 8; j++) {
                float vv = acc[i][j] + bv[j];
                if (MODE == 1) vv += res[(size_t)m * N + colBase + tx*8 + j];
                if (MODE == 2) vv = gelu_exact(vv);
                crow[j] = vv;
            }
        }
    }
}

// ---------------- MoE gate + routing (replicates softmax -> top2 -> softmax) ----------------
__global__ __launch_bounds__(128) void gate_route_kernel(
    const float* __restrict__ xn, const float* __restrict__ wg)
{
    int trow = blockIdx.x;
    const float* xr = xn + (size_t)trow * DD;
    float p[4] = {0.f, 0.f, 0.f, 0.f};
    for (int d = threadIdx.x; d < DD; d += 128) {
        float xv = xr[d];
#pragma unroll
        for (int e = 0; e < 4; e++) p[e] += xv * wg[d*4 + e];
    }
    __shared__ float red[4][128];
#pragma unroll
    for (int e = 0; e < 4; e++) red[e][threadIdx.x] = p[e];
    __syncthreads();
    for (int st = 64; st > 0; st >>= 1) {
        if (threadIdx.x < st)
#pragma unroll
            for (int e = 0; e < 4; e++) red[e][threadIdx.x] += red[e][threadIdx.x + st];
        __syncthreads();
    }
    if (threadIdx.x == 0) {
        float lg[4];
#pragma unroll
        for (int e = 0; e < 4; e++) lg[e] = red[e][0];
        float mx = fmaxf(fmaxf(lg[0], lg[1]), fmaxf(lg[2], lg[3]));
        float ex[4], ssum = 0.f;
#pragma unroll
        for (int e = 0; e < 4; e++) { ex[e] = expf(lg[e] - mx); ssum += ex[e]; }
        float pr[4];
#pragma unroll
        for (int e = 0; e < 4; e++) pr[e] = ex[e] / ssum;
        // top-2 (ties -> lower index, matching jax.lax.top_k)
        int i0 = 0;
        for (int e = 1; e < 4; e++) if (pr[e] > pr[i0]) i0 = e;
        int i1 = -1;
        for (int e = 0; e < 4; e++) if (e != i0 && (i1 < 0 || pr[e] > pr[i1])) i1 = e;
        // renormalize: softmax over (pr[i0], pr[i1]); pr[i0] >= pr[i1]
        float e1 = expf(pr[i1] - pr[i0]);
        float w0 = 1.f / (1.f + e1);
        float w1 = e1 / (1.f + e1);
        int s0 = atomicAdd(&g_cnt[i0], 1);
        g_tok[i0*TT + s0] = trow; g_w[i0*TT + s0] = w0;
        int s1 = atomicAdd(&g_cnt[i1], 1);
        g_tok[i1*TT + s1] = trow; g_w[i1*TT + s1] = w1;
    }
}

// ---------------- launch ----------------
extern "C" void kernel_launch(void* const* d_in, const int* in_sizes, int n_in,
                              void* d_out, int out_size) {
    const float* x    = (const float*)d_in[0];
    const float* wq   = (const float*)d_in[1];
    const float* bq   = (const float*)d_in[2];
    const float* wk   = (const float*)d_in[3];
    const float* bk   = (const float*)d_in[4];
    const float* wv   = (const float*)d_in[5];
    const float* bv   = (const float*)d_in[6];
    const float* wo   = (const float*)d_in[7];
    const float* bo   = (const float*)d_in[8];
    const float* ln1w = (const float*)d_in[9];
    const float* ln1b = (const float*)d_in[10];
    const float* ln2w = (const float*)d_in[11];
    const float* ln2b = (const float*)d_in[12];
    const float* wg   = (const float*)d_in[13];
    const float* we1  = (const float*)d_in[14];
    const float* be1  = (const float*)d_in[15];
    const float* we2  = (const float*)d_in[16];
    const float* be2  = (const float*)d_in[17];
    float* out = (float*)d_out;

    float *xn, *q, *k, *v, *attn, *h, *hmid, *tw;
    int *cnt, *tok;
    cudaGetSymbolAddress((void**)&xn,   g_xn);
    cudaGetSymbolAddress((void**)&q,    g_q);
    cudaGetSymbolAddress((void**)&k,    g_k);
    cudaGetSymbolAddress((void**)&v,    g_v);
    cudaGetSymbolAddress((void**)&attn, g_attn);
    cudaGetSymbolAddress((void**)&h,    g_h);
    cudaGetSymbolAddress((void**)&hmid, g_hmid);
    cudaGetSymbolAddress((void**)&cnt,  g_cnt);
    cudaGetSymbolAddress((void**)&tok,  g_tok);
    cudaGetSymbolAddress((void**)&tw,   g_w);

    zero_cnt_kernel<<<1, 32>>>();

    // LN1
    layernorm_kernel<<<TT, 256>>>(x, ln1w, ln1b, xn);

    // QKV projections
    dim3 gg(DD / 128, TT / 128);   // (16, 32)
    sgemm_kernel<0, false><<<gg, 256>>>(xn, wq, bq, q, nullptr, nullptr, nullptr, nullptr, nullptr, TT, DD, DD);
    sgemm_kernel<0, false><<<gg, 256>>>(xn, wk, bk, k, nullptr, nullptr, nullptr, nullptr, nullptr, TT, DD, DD);
    sgemm_kernel<0, false><<<gg, 256>>>(xn, wv, bv, v, nullptr, nullptr, nullptr, nullptr, nullptr, TT, DD, DD);

    // RoPE
    rope_kernel<<<(TT * HH * 64) / 256, 256>>>(q, k);

    // causal flash attention
    flash_kernel<<<dim3(SS / 64, BB * HH), 128>>>(q, k, v, attn);

    // O projection + residual -> h
    sgemm_kernel<1, false><<<gg, 256>>>(attn, wo, bo, h, x, nullptr, nullptr, nullptr, nullptr, TT, DD, DD);

    // out = h (MoE accumulates on top)
    copy_kernel<<<(TT * DD / 4 + 255) / 256, 256>>>((const float4*)h, (float4*)out, TT * DD / 4);

    // LN2
    layernorm_kernel<<<TT, 256>>>(h, ln2w, ln2b, xn);

    // gate + routing
    gate_route_kernel<<<TT, 128>>>(xn, wg);

    // experts: fc1 (gather + exact GELU) then fc2 (weighted scatter-accumulate)
    for (int e = 0; e < EE; e++) {
        sgemm_kernel<2, true><<<dim3(II / 128, TT / 128), 256>>>(
            xn, we1 + (size_t)e * DD * II, be1 + (size_t)e * II, hmid,
            nullptr, tok + e * TT, cnt + e, nullptr, nullptr, TT, II, DD);
        sgemm_kernel<3, false><<<dim3(DD / 128, TT / 128), 256>>>(
            hmid, we2 + (size_t)e * II * DD, be2 + (size_t)e * DD, out,
            nullptr, nullptr, cnt + e, tok + e * TT, tw + e * TT, TT, DD, II);
    }
}

// round 3
// speedup vs baseline: 3.9079x; 3.9079x over previous
#include <cuda_runtime.h>
#include <cuda_bf16.h>
#include <math.h>
#include <cstdint>

#define BB  2
#define SS  2048
#define DD  2048
#define HH  16
#define HDD 128
#define EE  4
#define II  2048
#define TT  (BB*SS)   // 4096 tokens

// ---------------- scratch (device globals) ----------------
__device__ float g_xn  [TT*DD];
__device__ float g_q   [TT*DD];
__device__ float g_k   [TT*DD];
__device__ float g_v   [TT*DD];
__device__ float g_attn[TT*DD];
__device__ float g_h   [TT*DD];
__device__ float g_hmid[TT*II];
__device__ int   g_cnt [EE];
__device__ int   g_tok [EE*TT];
__device__ float g_w   [EE*TT];
// transposed (tf32-rounded) weights, [N,K] K-major
__device__ float g_wqt [DD*DD];
__device__ float g_wkt [DD*DD];
__device__ float g_wvt [DD*DD];
__device__ float g_wot [DD*DD];
__device__ float g_we1t[EE*II*DD];
__device__ float g_we2t[EE*DD*II];

// ---------------- helpers ----------------
__device__ __forceinline__ uint32_t smem_u32(const void* p) {
    uint32_t a;
    asm("{ .reg .u64 t; cvta.to.shared.u64 t, %1; cvt.u32.u64 %0, t; }" : "=r"(a) : "l"(p));
    return a;
}
__device__ __forceinline__ float to_tf32(float x) {
    uint32_t r;
    asm("cvt.rna.tf32.f32 %0, %1;" : "=r"(r) : "f"(x));
    return __uint_as_float(r);
}
#define CP_ASYNC16(sa, ga) \
    asm volatile("cp.async.cg.shared.global [%0], [%1], 16;" :: "r"(sa), "l"(ga) : "memory")
#define CP_COMMIT()  asm volatile("cp.async.commit_group;" ::: "memory")
#define CP_WAIT0()   asm volatile("cp.async.wait_group 0;" ::: "memory")

__device__ __forceinline__ void mma_tf32(float* d, const uint32_t* a, const uint32_t* b) {
    asm volatile("mma.sync.aligned.m16n8k8.row.col.f32.tf32.tf32.f32 "
        "{%0,%1,%2,%3}, {%4,%5,%6,%7}, {%8,%9}, {%0,%1,%2,%3};"
        : "+f"(d[0]), "+f"(d[1]), "+f"(d[2]), "+f"(d[3])
        : "r"(a[0]), "r"(a[1]), "r"(a[2]), "r"(a[3]), "r"(b[0]), "r"(b[1]));
}

// ---------------- tiny kernels ----------------
__global__ void zero_cnt_kernel() {
    if (threadIdx.x < EE) g_cnt[threadIdx.x] = 0;
}
__global__ void copy_kernel(const float4* __restrict__ src, float4* __restrict__ dst, int n4) {
    int i = blockIdx.x * blockDim.x + threadIdx.x;
    if (i < n4) dst[i] = src[i];
}

// ---------------- weight transpose + tf32 round ----------------
__global__ __launch_bounds__(256) void transpose_tf32_kernel(const float* __restrict__ src, float* __restrict__ dst) {
    __shared__ float t[32][33];
    int cb = blockIdx.x * 32, rb = blockIdx.y * 32;
    int tx = threadIdx.x & 31, ty = threadIdx.x >> 5;
#pragma unroll
    for (int i = 0; i < 32; i += 8)
        t[ty + i][tx] = src[(size_t)(rb + ty + i) * DD + cb + tx];
    __syncthreads();
#pragma unroll
    for (int i = 0; i < 32; i += 8)
        dst[(size_t)(cb + ty + i) * DD + rb + tx] = to_tf32(t[tx][ty + i]);
}

// ---------------- LayerNorm ----------------
__global__ __launch_bounds__(256) void layernorm_kernel(
    const float* __restrict__ x, const float* __restrict__ w,
    const float* __restrict__ b, float* __restrict__ out)
{
    int row = blockIdx.x;
    const float* xr = x + (size_t)row * DD;
    int t = threadIdx.x;
    float v[8];
    float s = 0.f;
#pragma unroll
    for (int i = 0; i < 8; i++) { v[i] = xr[t + i*256]; s += v[i]; }
    __shared__ float red[256];
    red[t] = s; __syncthreads();
    for (int st = 128; st > 0; st >>= 1) {
        if (t < st) red[t] += red[t + st];
        __syncthreads();
    }
    float mu = red[0] * (1.f / DD);
    __syncthreads();
    float s2 = 0.f;
#pragma unroll
    for (int i = 0; i < 8; i++) { float dv = v[i] - mu; s2 += dv * dv; }
    red[t] = s2; __syncthreads();
    for (int st = 128; st > 0; st >>= 1) {
        if (t < st) red[t] += red[t + st];
        __syncthreads();
    }
    float rstd = rsqrtf(red[0] * (1.f / DD) + 1e-5f);
    float* orow = out + (size_t)row * DD;
#pragma unroll
    for (int i = 0; i < 8; i++) {
        int d = t + i*256;
        orow[d] = (v[i] - mu) * rstd * w[d] + b[d];
    }
}

// ---------------- RoPE ----------------
__global__ void rope_kernel(float* __restrict__ Q, float* __restrict__ K) {
    int i = blockIdx.x * blockDim.x + threadIdx.x;
    if (i >= TT * HH * 64) return;
    int di   = i & 63;
    int rest = i >> 6;
    int h    = rest & (HH - 1);
    int bs   = rest >> 4;
    int pos  = bs & (SS - 1);
    float invf = expf(-(float)di * 0.14391156516685623f);
    float ang  = (float)pos * invf;
    float sn, c;
    sincosf(ang, &sn, &c);
    size_t base = (size_t)bs * DD + h * HDD + di;
    float q1 = Q[base], q2 = Q[base + 64];
    Q[base]      = q1 * c - q2 * sn;
    Q[base + 64] = q2 * c + q1 * sn;
    float k1 = K[base], k2 = K[base + 64];
    K[base]      = k1 * c - k2 * sn;
    K[base + 64] = k2 * c + k1 * sn;
}

// ---------------- causal flash attention, fp32 ----------------
#define KPAD 132
__global__ __launch_bounds__(128) void flash_kernel(
    const float* __restrict__ Q, const float* __restrict__ K,
    const float* __restrict__ V, float* __restrict__ O)
{
    __shared__ float Ks[32][KPAD];
    __shared__ float Vs[32][KPAD];
    int bh = blockIdx.y;
    int b = bh >> 4, h = bh & 15;
    int q0 = blockIdx.x * 64;
    int t = threadIdx.x;
    int r = t >> 1, half = t & 1;
    int qg = q0 + r;
    size_t qoff = ((size_t)(b * SS + qg)) * DD + h * HDD + half * 64;
    float qreg[64];
#pragma unroll
    for (int d = 0; d < 64; d++) qreg[d] = Q[qoff + d];
    float acc[64];
#pragma unroll
    for (int d = 0; d < 64; d++) acc[d] = 0.f;
    float mval = -1e30f, l = 0.f;
    int nk = q0 + 64;
    int hb = half * 68;
    for (int j0 = 0; j0 < nk; j0 += 32) {
#pragma unroll
        for (int i = 0; i < 8; i++) {
            int idx = t + i * 128;
            int row = idx >> 5;
            int c4  = idx & 31;
            int co  = c4 * 4 + (c4 >= 16 ? 4 : 0);
            size_t g = ((size_t)(b * SS + j0 + row)) * DD + h * HDD + c4 * 4;
            *(float4*)&Ks[row][co] = *(const float4*)(K + g);
            *(float4*)&Vs[row][co] = *(const float4*)(V + g);
        }
        __syncthreads();
        float s[32];
#pragma unroll
        for (int j = 0; j < 32; j++) {
            float p = 0.f;
#pragma unroll
            for (int d = 0; d < 64; d++) p += qreg[d] * Ks[j][hb + d];
            p += __shfl_xor_sync(0xffffffffu, p, 1);
            float sc = p * 0.08838834764831845f;
            if (j0 + j > qg) sc = -1e30f;
            s[j] = sc;
        }
        float tmax = -1e30f;
#pragma unroll
        for (int j = 0; j < 32; j++) tmax = fmaxf(tmax, s[j]);
        float mnew = fmaxf(mval, tmax);
        float scale = __expf(mval - mnew);
        l *= scale;
#pragma unroll
        for (int d = 0; d < 64; d++) acc[d] *= scale;
#pragma unroll
        for (int j = 0; j < 32; j++) {
            float p = __expf(s[j] - mnew);
            l += p;
#pragma unroll
            for (int d = 0; d < 64; d++) acc[d] += p * Vs[j][hb + d];
        }
        mval = mnew;
        __syncthreads();
    }
    float inv = 1.f / l;
#pragma unroll
    for (int d = 0; d < 64; d++) O[qoff + d] = acc[d] * inv;
}

// ---------------- tf32 mma.sync GEMM: C[M,N] = A[M,K] * Bt[N,K]^T + epilogue ----------------
// MODE 0: C = acc + bias
// MODE 1: C = acc + bias + res
// MODE 2: C = gelu(acc + bias)   (GATHER: A rows via gatherIdx)
// MODE 3: C[scatterIdx[m]] += w[m]*(acc + bias)
// 256 threads, block tile 128x128, warp grid 2(m)x4(n), warp tile 64x32, K chunks of 32.
__device__ __forceinline__ float gelu_exact(float x) {
    return 0.5f * x * (1.0f + erff(x * 0.70710678118654752f));
}

#define KPAD36 36
#define TILE_FLOATS (128 * KPAD36)            // 4608 floats per operand tile
#define STAGE_FLOATS (2 * TILE_FLOATS)        // A + B
#define GEMM_SMEM_BYTES (2 * STAGE_FLOATS * 4)  // 73728 bytes

template<int MODE, bool GATHER>
__global__ __launch_bounds__(256, 1) void mma_gemm_kernel(
    const float* __restrict__ A, const float* __restrict__ Bt, const float* __restrict__ bias,
    float* __restrict__ C, const float* __restrict__ res,
    const int* __restrict__ gatherIdx, const int* __restrict__ cntPtr,
    const int* __restrict__ scatterIdx, const float* __restrict__ scatterW,
    int M, int N, int K)
{
    extern __shared__ float smem[];
    int Meff = cntPtr ? *cntPtr : M;
    int rowBase = blockIdx.y * 128;
    if (rowBase >= Meff) return;
    int colBase = blockIdx.x * 128;

    int tid  = threadIdx.x;
    int lane = tid & 31;
    int wid  = tid >> 5;
    int warpM = wid & 1, warpN = wid >> 1;    // 2 x 4
    int gr = lane >> 2, gc = lane & 3;        // fragment row/col basis

    // tile-load mapping: q = 16B chunk in row (8 per row of 32 floats), 4 rows per thread
    int q  = tid & 7;
    int r0 = tid >> 3;       // 0..31; rows r0 + 32*i
    const float* aptr[4];
    const float* bptr[4];
#pragma unroll
    for (int i = 0; i < 4; i++) {
        int row = r0 + 32 * i;
        int m = rowBase + row; if (m > Meff - 1) m = Meff - 1;
        int arow = GATHER ? gatherIdx[m] : m;
        aptr[i] = A  + (size_t)arow * K + q * 4;
        bptr[i] = Bt + (size_t)(colBase + row) * K + q * 4;
    }

    float acc[4][4][4];
#pragma unroll
    for (int a = 0; a < 4; a++)
#pragma unroll
        for (int b = 0; b < 4; b++)
#pragma unroll
            for (int c = 0; c < 4; c++) acc[a][b][c] = 0.f;

    const int nIter = K / 32;

    // prologue: fill stage 0
    {
        float* As = smem;
        float* Bs = smem + TILE_FLOATS;
        float4 ar[4];
#pragma unroll
        for (int i = 0; i < 4; i++) ar[i] = *(const float4*)(aptr[i]);
#pragma unroll
        for (int i = 0; i < 4; i++)
            CP_ASYNC16(smem_u32(Bs + (r0 + 32*i) * KPAD36 + q * 4), bptr[i]);
        CP_COMMIT();
#pragma unroll
        for (int i = 0; i < 4; i++) {
            float4 t;
            t.x = to_tf32(ar[i].x); t.y = to_tf32(ar[i].y);
            t.z = to_tf32(ar[i].z); t.w = to_tf32(ar[i].w);
            *(float4*)(As + (r0 + 32*i) * KPAD36 + q * 4) = t;
        }
        CP_WAIT0();
        __syncthreads();
    }

    for (int it = 0; it < nIter; it++) {
        int s = it & 1, ns = s ^ 1;
        bool more = (it + 1 < nIter);
        float* As  = smem + s  * STAGE_FLOATS;
        float* Bs  = As + TILE_FLOATS;
        float* Asn = smem + ns * STAGE_FLOATS;
        float* Bsn = Asn + TILE_FLOATS;

        float4 ar[4];
        if (more) {
            int k0 = (it + 1) * 32;
#pragma unroll
            for (int i = 0; i < 4; i++) ar[i] = *(const float4*)(aptr[i] + k0);
#pragma unroll
            for (int i = 0; i < 4; i++)
                CP_ASYNC16(smem_u32(Bsn + (r0 + 32*i) * KPAD36 + q * 4), bptr[i] + k0);
            CP_COMMIT();
        }

        // MMA over 4 k-steps of 8
        const float* Aw = As + (warpM * 64 + gr) * KPAD36 + gc;
        const float* Bw = Bs + (warpN * 32 + gr) * KPAD36 + gc;
#pragma unroll
        for (int ks = 0; ks < 4; ks++) {
            uint32_t af[4][4];
            uint32_t bf[4][2];
#pragma unroll
            for (int mf = 0; mf < 4; mf++) {
                const float* p = Aw + mf * 16 * KPAD36 + ks * 8;
                af[mf][0] = __float_as_uint(p[0]);
                af[mf][1] = __float_as_uint(p[8 * KPAD36]);
                af[mf][2] = __float_as_uint(p[4]);
                af[mf][3] = __float_as_uint(p[8 * KPAD36 + 4]);
            }
#pragma unroll
            for (int nf = 0; nf < 4; nf++) {
                const float* p = Bw + nf * 8 * KPAD36 + ks * 8;
                bf[nf][0] = __float_as_uint(p[0]);
                bf[nf][1] = __float_as_uint(p[4]);
            }
#pragma unroll
            for (int mf = 0; mf < 4; mf++)
#pragma unroll
                for (int nf = 0; nf < 4; nf++)
                    mma_tf32(acc[mf][nf], af[mf], bf[nf]);
        }

        if (more) {
#pragma unroll
            for (int i = 0; i < 4; i++) {
                float4 t;
                t.x = to_tf32(ar[i].x); t.y = to_tf32(ar[i].y);
                t.z = to_tf32(ar[i].z); t.w = to_tf32(ar[i].w);
                *(float4*)(Asn + (r0 + 32*i) * KPAD36 + q * 4) = t;
            }
            CP_WAIT0();
        }
        __syncthreads();
    }

    // ---------------- epilogue ----------------
    // acc[mf][nf]: rows rowBase + warpM*64 + mf*16 + gr (+8); cols colBase + warpN*32 + nf*8 + gc*2 (+1)
#pragma unroll
    for (int mf = 0; mf < 4; mf++) {
#pragma unroll
        for (int half = 0; half < 2; half++) {
            int m = rowBase + warpM * 64 + mf * 16 + gr + half * 8;
            if (m >= Meff) continue;
            if (MODE == 3) {
                int trow = scatterIdx[m];
                float wgt = scatterW[m];
                float* crow = C + (size_t)trow * N;
#pragma unroll
                for (int nf = 0; nf < 4; nf++) {
                    int col = colBase + warpN * 32 + nf * 8 + gc * 2;
                    float v0 = acc[mf][nf][half*2+0] + bias[col];
                    float v1 = acc[mf][nf][half*2+1] + bias[col+1];
                    crow[col]   += wgt * v0;
                    crow[col+1] += wgt * v1;
                }
            } else {
                float* crow = C + (size_t)m * N;
                const float* rrow = (MODE == 1) ? (res + (size_t)m * N) : nullptr;
#pragma unroll
                for (int nf = 0; nf < 4; nf++) {
                    int col = colBase + warpN * 32 + nf * 8 + gc * 2;
                    float v0 = acc[mf][nf][half*2+0] + bias[col];
                    float v1 = acc[mf][nf][half*2+1] + bias[col+1];
                    if (MODE == 1) { v0 += rrow[col]; v1 += rrow[col+1]; }
                    if (MODE == 2) { v0 = gelu_exact(v0); v1 = gelu_exact(v1); }
                    crow[col]   = v0;
                    crow[col+1] = v1;
                }
            }
        }
    }
}

// ---------------- MoE gate + routing ----------------
__global__ __launch_bounds__(128) void gate_route_kernel(
    const float* __restrict__ xn, const float* __restrict__ wg)
{
    int trow = blockIdx.x;
    const float* xr = xn + (size_t)trow * DD;
    float p[4] = {0.f, 0.f, 0.f, 0.f};
    for (int d = threadIdx.x; d < DD; d += 128) {
        float xv = xr[d];
#pragma unroll
        for (int e = 0; e < 4; e++) p[e] += xv * wg[d*4 + e];
    }
    __shared__ float red[4][128];
#pragma unroll
    for (int e = 0; e < 4; e++) red[e][threadIdx.x] = p[e];
    __syncthreads();
    for (int st = 64; st > 0; st >>= 1) {
        if (threadIdx.x < st)
#pragma unroll
            for (int e = 0; e < 4; e++) red[e][threadIdx.x] += red[e][threadIdx.x + st];
        __syncthreads();
    }
    if (threadIdx.x == 0) {
        float lg[4];
#pragma unroll
        for (int e = 0; e < 4; e++) lg[e] = red[e][0];
        float mx = fmaxf(fmaxf(lg[0], lg[1]), fmaxf(lg[2], lg[3]));
        float ex[4], ssum = 0.f;
#pragma unroll
        for (int e = 0; e < 4; e++) { ex[e] = expf(lg[e] - mx); ssum += ex[e]; }
        float pr[4];
#pragma unroll
        for (int e = 0; e < 4; e++) pr[e] = ex[e] / ssum;
        int i0 = 0;
        for (int e = 1; e < 4; e++) if (pr[e] > pr[i0]) i0 = e;
        int i1 = -1;
        for (int e = 0; e < 4; e++) if (e != i0 && (i1 < 0 || pr[e] > pr[i1])) i1 = e;
        float e1 = expf(pr[i1] - pr[i0]);
        float w0 = 1.f / (1.f + e1);
        float w1 = e1 / (1.f + e1);
        int s0 = atomicAdd(&g_cnt[i0], 1);
        g_tok[i0*TT + s0] = trow; g_w[i0*TT + s0] = w0;
        int s1 = atomicAdd(&g_cnt[i1], 1);
        g_tok[i1*TT + s1] = trow; g_w[i1*TT + s1] = w1;
    }
}

// ---------------- launch ----------------
extern "C" void kernel_launch(void* const* d_in, const int* in_sizes, int n_in,
                              void* d_out, int out_size) {
    const float* x    = (const float*)d_in[0];
    const float* wq   = (const float*)d_in[1];
    const float* bq   = (const float*)d_in[2];
    const float* wk   = (const float*)d_in[3];
    const float* bk   = (const float*)d_in[4];
    const float* wv   = (const float*)d_in[5];
    const float* bv   = (const float*)d_in[6];
    const float* wo   = (const float*)d_in[7];
    const float* bo   = (const float*)d_in[8];
    const float* ln1w = (const float*)d_in[9];
    const float* ln1b = (const float*)d_in[10];
    const float* ln2w = (const float*)d_in[11];
    const float* ln2b = (const float*)d_in[12];
    const float* wg   = (const float*)d_in[13];
    const float* we1  = (const float*)d_in[14];
    const float* be1  = (const float*)d_in[15];
    const float* we2  = (const float*)d_in[16];
    const float* be2  = (const float*)d_in[17];
    float* out = (float*)d_out;

    float *xn, *q, *k, *v, *attn, *h, *hmid, *tw;
    float *wqt, *wkt, *wvt, *wot, *we1t, *we2t;
    int *cnt, *tok;
    cudaGetSymbolAddress((void**)&xn,   g_xn);
    cudaGetSymbolAddress((void**)&q,    g_q);
    cudaGetSymbolAddress((void**)&k,    g_k);
    cudaGetSymbolAddress((void**)&v,    g_v);
    cudaGetSymbolAddress((void**)&attn, g_attn);
    cudaGetSymbolAddress((void**)&h,    g_h);
    cudaGetSymbolAddress((void**)&hmid, g_hmid);
    cudaGetSymbolAddress((void**)&cnt,  g_cnt);
    cudaGetSymbolAddress((void**)&tok,  g_tok);
    cudaGetSymbolAddress((void**)&tw,   g_w);
    cudaGetSymbolAddress((void**)&wqt,  g_wqt);
    cudaGetSymbolAddress((void**)&wkt,  g_wkt);
    cudaGetSymbolAddress((void**)&wvt,  g_wvt);
    cudaGetSymbolAddress((void**)&wot,  g_wot);
    cudaGetSymbolAddress((void**)&we1t, g_we1t);
    cudaGetSymbolAddress((void**)&we2t, g_we2t);

    cudaFuncSetAttribute(mma_gemm_kernel<0, false>, cudaFuncAttributeMaxDynamicSharedMemorySize, GEMM_SMEM_BYTES);
    cudaFuncSetAttribute(mma_gemm_kernel<1, false>, cudaFuncAttributeMaxDynamicSharedMemorySize, GEMM_SMEM_BYTES);
    cudaFuncSetAttribute(mma_gemm_kernel<2, true >, cudaFuncAttributeMaxDynamicSharedMemorySize, GEMM_SMEM_BYTES);
    cudaFuncSetAttribute(mma_gemm_kernel<3, false>, cudaFuncAttributeMaxDynamicSharedMemorySize, GEMM_SMEM_BYTES);

    zero_cnt_kernel<<<1, 32>>>();

    // transpose + tf32-round all weights into [N,K]
    dim3 tg(DD / 32, DD / 32);
    transpose_tf32_kernel<<<tg, 256>>>(wq, wqt);
    transpose_tf32_kernel<<<tg, 256>>>(wk, wkt);
    transpose_tf32_kernel<<<tg, 256>>>(wv, wvt);
    transpose_tf32_kernel<<<tg, 256>>>(wo, wot);
    for (int e = 0; e < EE; e++) {
        transpose_tf32_kernel<<<tg, 256>>>(we1 + (size_t)e * DD * II, we1t + (size_t)e * II * DD);
        transpose_tf32_kernel<<<tg, 256>>>(we2 + (size_t)e * II * DD, we2t + (size_t)e * DD * II);
    }

    // LN1
    layernorm_kernel<<<TT, 256>>>(x, ln1w, ln1b, xn);

    // QKV projections (tensor cores, tf32)
    dim3 gg(DD / 128, TT / 128);   // (16, 32)
    mma_gemm_kernel<0, false><<<gg, 256, GEMM_SMEM_BYTES>>>(xn, wqt, bq, q, nullptr, nullptr, nullptr, nullptr, nullptr, TT, DD, DD);
    mma_gemm_kernel<0, false><<<gg, 256, GEMM_SMEM_BYTES>>>(xn, wkt, bk, k, nullptr, nullptr, nullptr, nullptr, nullptr, TT, DD, DD);
    mma_gemm_kernel<0, false><<<gg, 256, GEMM_SMEM_BYTES>>>(xn, wvt, bv, v, nullptr, nullptr, nullptr, nullptr, nullptr, TT, DD, DD);

    // RoPE
    rope_kernel<<<(TT * HH * 64) / 256, 256>>>(q, k);

    // causal flash attention
    flash_kernel<<<dim3(SS / 64, BB * HH), 128>>>(q, k, v, attn);

    // O projection + residual -> h
    mma_gemm_kernel<1, false><<<gg, 256, GEMM_SMEM_BYTES>>>(attn, wot, bo, h, x, nullptr, nullptr, nullptr, nullptr, TT, DD, DD);

    // out = h (MoE accumulates on top)
    copy_kernel<<<(TT * DD / 4 + 255) / 256, 256>>>((const float4*)h, (float4*)out, TT * DD / 4);

    // LN2
    layernorm_kernel<<<TT, 256>>>(h, ln2w, ln2b, xn);

    // gate + routing
    gate_route_kernel<<<TT, 128>>>(xn, wg);

    // experts
    for (int e = 0; e < EE; e++) {
        mma_gemm_kernel<2, true><<<dim3(II / 128, TT / 128), 256, GEMM_SMEM_BYTES>>>(
            xn, we1t + (size_t)e * II * DD, be1 + (size_t)e * II, hmid,
            nullptr, tok + e * TT, cnt + e, nullptr, nullptr, TT, II, DD);
        mma_gemm_kernel<3, false><<<dim3(DD / 128, TT / 128), 256, GEMM_SMEM_BYTES>>>(
            hmid, we2t + (size_t)e * DD * II, be2 + (size_t)e * DD, out,
            nullptr, nullptr, cnt + e, tok + e * TT, tw + e * TT, TT, DD, II);
    }
}

// round 5
// speedup vs baseline: 6.2307x; 1.5944x over previous
#include <cuda_runtime.h>
#include <cuda_bf16.h>
#include <math.h>
#include <cstdint>

#define BB  2
#define SS  2048
#define DD  2048
#define HH  16
#define HDD 128
#define EE  4
#define II  2048
#define TT  (BB*SS)   // 4096 tokens

// ---------------- scratch (device globals) ----------------
__device__ float g_xn  [TT*DD];
__device__ float g_q   [TT*DD];
__device__ float g_k   [TT*DD];
__device__ float g_v   [TT*DD];
__device__ float g_attn[TT*DD];
__device__ float g_h   [TT*DD];
__device__ float g_hmid[TT*II];
__device__ int   g_cnt [EE];
__device__ int   g_tok [EE*TT];
__device__ float g_w   [EE*TT];
// transposed (tf32-rounded) weights, [N,K] K-major
__device__ float g_wqt [DD*DD];
__device__ float g_wkt [DD*DD];
__device__ float g_wvt [DD*DD];
__device__ float g_wot [DD*DD];
__device__ float g_we1t[EE*II*DD];
__device__ float g_we2t[EE*DD*II];

// ---------------- helpers ----------------
__device__ __forceinline__ uint32_t smem_u32(const void* p) {
    uint32_t a;
    asm("{ .reg .u64 t; cvta.to.shared.u64 t, %1; cvt.u32.u64 %0, t; }" : "=r"(a) : "l"(p));
    return a;
}
__device__ __forceinline__ float to_tf32(float x) {
    uint32_t r;
    asm("cvt.rna.tf32.f32 %0, %1;" : "=r"(r) : "f"(x));
    return __uint_as_float(r);
}
#define CP_ASYNC16(sa, ga) \
    asm volatile("cp.async.cg.shared.global [%0], [%1], 16;" :: "r"(sa), "l"(ga) : "memory")
#define CP_COMMIT()  asm volatile("cp.async.commit_group;" ::: "memory")
#define CP_WAIT0()   asm volatile("cp.async.wait_group 0;" ::: "memory")
#define CP_WAIT1()   asm volatile("cp.async.wait_group 1;" ::: "memory")

__device__ __forceinline__ void mma_tf32(float* d, const uint32_t* a, const uint32_t* b) {
    asm volatile("mma.sync.aligned.m16n8k8.row.col.f32.tf32.tf32.f32 "
        "{%0,%1,%2,%3}, {%4,%5,%6,%7}, {%8,%9}, {%0,%1,%2,%3};"
        : "+f"(d[0]), "+f"(d[1]), "+f"(d[2]), "+f"(d[3])
        : "r"(a[0]), "r"(a[1]), "r"(a[2]), "r"(a[3]), "r"(b[0]), "r"(b[1]));
}

// ---------------- tiny kernels ----------------
__global__ void zero_cnt_kernel() {
    if (threadIdx.x < EE) g_cnt[threadIdx.x] = 0;
}
__global__ void copy_kernel(const float4* __restrict__ src, float4* __restrict__ dst, int n4) {
    int i = blockIdx.x * blockDim.x + threadIdx.x;
    if (i < n4) dst[i] = src[i];
}

// ---------------- weight transpose + tf32 round ----------------
__global__ __launch_bounds__(256) void transpose_tf32_kernel(const float* __restrict__ src, float* __restrict__ dst) {
    __shared__ float t[32][33];
    int cb = blockIdx.x * 32, rb = blockIdx.y * 32;
    int tx = threadIdx.x & 31, ty = threadIdx.x >> 5;
#pragma unroll
    for (int i = 0; i < 32; i += 8)
        t[ty + i][tx] = src[(size_t)(rb + ty + i) * DD + cb + tx];
    __syncthreads();
#pragma unroll
    for (int i = 0; i < 32; i += 8)
        dst[(size_t)(cb + ty + i) * DD + rb + tx] = to_tf32(t[tx][ty + i]);
}

// ---------------- LayerNorm ----------------
__global__ __launch_bounds__(256) void layernorm_kernel(
    const float* __restrict__ x, const float* __restrict__ w,
    const float* __restrict__ b, float* __restrict__ out)
{
    int row = blockIdx.x;
    const float* xr = x + (size_t)row * DD;
    int t = threadIdx.x;
    float v[8];
    float s = 0.f;
#pragma unroll
    for (int i = 0; i < 8; i++) { v[i] = xr[t + i*256]; s += v[i]; }
    __shared__ float red[256];
    red[t] = s; __syncthreads();
    for (int st = 128; st > 0; st >>= 1) {
        if (t < st) red[t] += red[t + st];
        __syncthreads();
    }
    float mu = red[0] * (1.f / DD);
    __syncthreads();
    float s2 = 0.f;
#pragma unroll
    for (int i = 0; i < 8; i++) { float dv = v[i] - mu; s2 += dv * dv; }
    red[t] = s2; __syncthreads();
    for (int st = 128; st > 0; st >>= 1) {
        if (t < st) red[t] += red[t + st];
        __syncthreads();
    }
    float rstd = rsqrtf(red[0] * (1.f / DD) + 1e-5f);
    float* orow = out + (size_t)row * DD;
#pragma unroll
    for (int i = 0; i < 8; i++) {
        int d = t + i*256;
        orow[d] = (v[i] - mu) * rstd * w[d] + b[d];
    }
}

// ---------------- RoPE (rounds Q,K to tf32 for the MMA flash) ----------------
__global__ void rope_kernel(float* __restrict__ Q, float* __restrict__ K) {
    int i = blockIdx.x * blockDim.x + threadIdx.x;
    if (i >= TT * HH * 64) return;
    int di   = i & 63;
    int rest = i >> 6;
    int h    = rest & (HH - 1);
    int bs   = rest >> 4;
    int pos  = bs & (SS - 1);
    float invf = expf(-(float)di * 0.14391156516685623f);
    float ang  = (float)pos * invf;
    float sn, c;
    sincosf(ang, &sn, &c);
    size_t base = (size_t)bs * DD + h * HDD + di;
    float q1 = Q[base], q2 = Q[base + 64];
    Q[base]      = to_tf32(q1 * c - q2 * sn);
    Q[base + 64] = to_tf32(q2 * c + q1 * sn);
    float k1 = K[base], k2 = K[base + 64];
    K[base]      = to_tf32(k1 * c - k2 * sn);
    K[base + 64] = to_tf32(k2 * c + k1 * sn);
}

// ---------------- tensor-core causal flash attention (tf32 mma.sync) ----------------
// block: 256 threads / 8 warps; Q tile 128 rows (warp w -> rows w*16..+15);
// K/V tile 64 keys, double-buffered cp.async. One (b,h) per blockIdx.y.
#define FQT   128
#define FKT   64
#define FPAD  132     // K & Q staging pad (frag banks 4*gr+gc -> conflict-free)
#define FPADV 136     // V pad (banks 8*gc+gr -> conflict-free)
#define PPAD  68
#define FLASH_SMEM ((2*64*FPAD + 2*64*FPADV + 8*16*PPAD) * 4)

__global__ __launch_bounds__(256, 1) void flash_mma_kernel(
    const float* __restrict__ Q, const float* __restrict__ K,
    const float* __restrict__ V, float* __restrict__ O)
{
    extern __shared__ float fs[];
    float* KsBase = fs;                       // [2][64][FPAD]
    float* VsBase = fs + 2*64*FPAD;           // [2][64][FPADV]
    float* Ps     = fs + 2*64*FPAD + 2*64*FPADV;  // [8][16][PPAD]

    int tid = threadIdx.x;
    int lane = tid & 31, w = tid >> 5;
    int gr = lane >> 2, gc = lane & 3;
    int bh = blockIdx.y;
    int b = bh >> 4, h = bh & 15;
    int xb = gridDim.x - 1 - blockIdx.x;      // big causal blocks first
    int q0 = xb * FQT;

    const float* Qg = Q + ((size_t)(b * SS + q0)) * DD + h * HDD;
    // stage Q tile 128x128 into KsBase (contiguous 128*FPAD region)
#pragma unroll
    for (int i = 0; i < 16; i++) {
        int idx = tid + i * 256;
        int row = idx >> 5, c4 = idx & 31;
        CP_ASYNC16(smem_u32(KsBase + row * FPAD + c4 * 4), Qg + (size_t)row * DD + c4 * 4);
    }
    CP_COMMIT(); CP_WAIT0();
    __syncthreads();

    uint32_t qf[16][4];
    {
        const float* r0 = KsBase + (w * 16 + gr) * FPAD;
        const float* r1 = KsBase + (w * 16 + gr + 8) * FPAD;
#pragma unroll
        for (int ks = 0; ks < 16; ks++) {
            qf[ks][0] = __float_as_uint(r0[ks * 8 + gc]);
            qf[ks][1] = __float_as_uint(r1[ks * 8 + gc]);
            qf[ks][2] = __float_as_uint(r0[ks * 8 + gc + 4]);
            qf[ks][3] = __float_as_uint(r1[ks * 8 + gc + 4]);
        }
    }
    __syncthreads();

    float oacc[16][4];
#pragma unroll
    for (int nt = 0; nt < 16; nt++)
#pragma unroll
        for (int e = 0; e < 4; e++) oacc[nt][e] = 0.f;
    float m0 = -1e30f, m1 = -1e30f, l0 = 0.f, l1 = 0.f;
    int nt_k = 2 * xb + 2;

    const float* Kg = K + ((size_t)(b * SS)) * DD + h * HDD;
    const float* Vg = V + ((size_t)(b * SS)) * DD + h * HDD;

    // prefetch tile 0 into buffer 0
#pragma unroll
    for (int i = 0; i < 8; i++) {
        int idx = tid + i * 256;
        int row = idx >> 5, c4 = idx & 31;
        CP_ASYNC16(smem_u32(KsBase + row * FPAD  + c4 * 4), Kg + (size_t)row * DD + c4 * 4);
        CP_ASYNC16(smem_u32(VsBase + row * FPADV + c4 * 4), Vg + (size_t)row * DD + c4 * 4);
    }
    CP_COMMIT();

    int row0 = q0 + w * 16 + gr, row1 = row0 + 8;
    const float SCL = 0.08838834764831845f;   // 1/sqrt(128)

    for (int t = 0; t < nt_k; t++) {
        int buf = t & 1;
        if (t + 1 < nt_k) {
            size_t off = (size_t)(t + 1) * FKT * DD;
            float* Kd = KsBase + (buf ^ 1) * 64 * FPAD;
            float* Vd = VsBase + (buf ^ 1) * 64 * FPADV;
#pragma unroll
            for (int i = 0; i < 8; i++) {
                int idx = tid + i * 256;
                int row = idx >> 5, c4 = idx & 31;
                CP_ASYNC16(smem_u32(Kd + row * FPAD  + c4 * 4), Kg + off + (size_t)row * DD + c4 * 4);
                CP_ASYNC16(smem_u32(Vd + row * FPADV + c4 * 4), Vg + off + (size_t)row * DD + c4 * 4);
            }
            CP_COMMIT();
            CP_WAIT1();
        } else {
            CP_WAIT0();
        }
        __syncthreads();
        const float* Kb = KsBase + buf * 64 * FPAD;
        const float* Vb = VsBase + buf * 64 * FPADV;

        // ---- S = Q K^T ----
        float sc[8][4];
#pragma unroll
        for (int nf = 0; nf < 8; nf++)
#pragma unroll
            for (int e = 0; e < 4; e++) sc[nf][e] = 0.f;
#pragma unroll
        for (int ks = 0; ks < 16; ks++) {
            uint32_t bf[8][2];
#pragma unroll
            for (int nf = 0; nf < 8; nf++) {
                const float* kp = Kb + (nf * 8 + gr) * FPAD + ks * 8 + gc;
                bf[nf][0] = __float_as_uint(kp[0]);
                bf[nf][1] = __float_as_uint(kp[4]);
            }
#pragma unroll
            for (int nf = 0; nf < 8; nf++)
                mma_tf32(sc[nf], qf[ks], bf[nf]);
        }
        // ---- scale + causal mask ----
        int j0 = t * FKT;
#pragma unroll
        for (int nf = 0; nf < 8; nf++) {
            int c0 = j0 + nf * 8 + gc * 2, c1 = c0 + 1;
            sc[nf][0] = (c0 <= row0) ? sc[nf][0] * SCL : -1e30f;
            sc[nf][1] = (c1 <= row0) ? sc[nf][1] * SCL : -1e30f;
            sc[nf][2] = (c0 <= row1) ? sc[nf][2] * SCL : -1e30f;
            sc[nf][3] = (c1 <= row1) ? sc[nf][3] * SCL : -1e30f;
        }
        // ---- online softmax ----
        float tm0 = -1e30f, tm1 = -1e30f;
#pragma unroll
        for (int nf = 0; nf < 8; nf++) {
            tm0 = fmaxf(tm0, fmaxf(sc[nf][0], sc[nf][1]));
            tm1 = fmaxf(tm1, fmaxf(sc[nf][2], sc[nf][3]));
        }
        tm0 = fmaxf(tm0, __shfl_xor_sync(0xffffffffu, tm0, 1));
        tm0 = fmaxf(tm0, __shfl_xor_sync(0xffffffffu, tm0, 2));
        tm1 = fmaxf(tm1, __shfl_xor_sync(0xffffffffu, tm1, 1));
        tm1 = fmaxf(tm1, __shfl_xor_sync(0xffffffffu, tm1, 2));
        float mn0 = fmaxf(m0, tm0), mn1 = fmaxf(m1, tm1);
        float rs0 = __expf(m0 - mn0), rs1 = __expf(m1 - mn1);
        l0 *= rs0; l1 *= rs1;
#pragma unroll
        for (int nt = 0; nt < 16; nt++) {
            oacc[nt][0] *= rs0; oacc[nt][1] *= rs0;
            oacc[nt][2] *= rs1; oacc[nt][3] *= rs1;
        }
        float* pr0 = Ps + (w * 16 + gr) * PPAD;
        float* pr1 = pr0 + 8 * PPAD;
        float s0 = 0.f, s1 = 0.f;
#pragma unroll
        for (int nf = 0; nf < 8; nf++) {
            float p0 = __expf(sc[nf][0] - mn0), p1 = __expf(sc[nf][1] - mn0);
            float p2 = __expf(sc[nf][2] - mn1), p3 = __expf(sc[nf][3] - mn1);
            s0 += p0 + p1; s1 += p2 + p3;
            *(float2*)(pr0 + nf * 8 + gc * 2) = make_float2(to_tf32(p0), to_tf32(p1));
            *(float2*)(pr1 + nf * 8 + gc * 2) = make_float2(to_tf32(p2), to_tf32(p3));
        }
        s0 += __shfl_xor_sync(0xffffffffu, s0, 1);
        s0 += __shfl_xor_sync(0xffffffffu, s0, 2);
        s1 += __shfl_xor_sync(0xffffffffu, s1, 1);
        s1 += __shfl_xor_sync(0xffffffffu, s1, 2);
        l0 += s0; l1 += s1; m0 = mn0; m1 = mn1;
        __syncwarp();
        // ---- O += P V ----
        const float* pw = Ps + w * 16 * PPAD;
#pragma unroll
        for (int ks = 0; ks < 8; ks++) {
            uint32_t af[4];
            af[0] = __float_as_uint(pw[gr * PPAD + ks * 8 + gc]);
            af[1] = __float_as_uint(pw[(gr + 8) * PPAD + ks * 8 + gc]);
            af[2] = __float_as_uint(pw[gr * PPAD + ks * 8 + gc + 4]);
            af[3] = __float_as_uint(pw[(gr + 8) * PPAD + ks * 8 + gc + 4]);
#pragma unroll
            for (int nt = 0; nt < 16; nt++) {
                uint32_t bf[2];
                bf[0] = __float_as_uint(Vb[(ks * 8 + gc) * FPADV + nt * 8 + gr]);
                bf[1] = __float_as_uint(Vb[(ks * 8 + gc + 4) * FPADV + nt * 8 + gr]);
                mma_tf32(oacc[nt], af, bf);
            }
        }
        __syncthreads();
    }
    float i0 = 1.f / l0, i1 = 1.f / l1;
    float* O0 = O + ((size_t)(b * SS + row0)) * DD + h * HDD;
    float* O1 = O + ((size_t)(b * SS + row1)) * DD + h * HDD;
#pragma unroll
    for (int nt = 0; nt < 16; nt++) {
        int c = nt * 8 + gc * 2;
        *(float2*)(O0 + c) = make_float2(oacc[nt][0] * i0, oacc[nt][1] * i0);
        *(float2*)(O1 + c) = make_float2(oacc[nt][2] * i1, oacc[nt][3] * i1);
    }
}

// ---------------- tf32 mma.sync GEMM ----------------
// MODE 0: C = acc + bias
// MODE 1: C = acc + bias + res
// MODE 2: C = gelu(acc + bias)   (GATHER: A rows via gatherIdx)
// MODE 3: C[scatterIdx[m]] += w[m]*(acc + bias)
// MODE 4: C = tf32(acc + bias)   (V projection; flash consumes tf32 operands)
__device__ __forceinline__ float gelu_exact(float x) {
    return 0.5f * x * (1.0f + erff(x * 0.70710678118654752f));
}

#define KPAD36 36
#define TILE_FLOATS (128 * KPAD36)
#define STAGE_FLOATS (2 * TILE_FLOATS)
#define GEMM_SMEM_BYTES (2 * STAGE_FLOATS * 4)

template<int MODE, bool GATHER>
__global__ __launch_bounds__(256, 1) void mma_gemm_kernel(
    const float* __restrict__ A, const float* __restrict__ Bt, const float* __restrict__ bias,
    float* __restrict__ C, const float* __restrict__ res,
    const int* __restrict__ gatherIdx, const int* __restrict__ cntPtr,
    const int* __restrict__ scatterIdx, const float* __restrict__ scatterW,
    int M, int N, int K)
{
    extern __shared__ float smem[];
    int Meff = cntPtr ? *cntPtr : M;
    int rowBase = blockIdx.y * 128;
    if (rowBase >= Meff) return;
    int colBase = blockIdx.x * 128;

    int tid  = threadIdx.x;
    int lane = tid & 31;
    int wid  = tid >> 5;
    int warpM = wid & 1, warpN = wid >> 1;
    int gr = lane >> 2, gc = lane & 3;

    int q  = tid & 7;
    int r0 = tid >> 3;
    const float* aptr[4];
    const float* bptr[4];
#pragma unroll
    for (int i = 0; i < 4; i++) {
        int row = r0 + 32 * i;
        int m = rowBase + row; if (m > Meff - 1) m = Meff - 1;
        int arow = GATHER ? gatherIdx[m] : m;
        aptr[i] = A  + (size_t)arow * K + q * 4;
        bptr[i] = Bt + (size_t)(colBase + row) * K + q * 4;
    }

    float acc[4][4][4];
#pragma unroll
    for (int a = 0; a < 4; a++)
#pragma unroll
        for (int b = 0; b < 4; b++)
#pragma unroll
            for (int c = 0; c < 4; c++) acc[a][b][c] = 0.f;

    const int nIter = K / 32;

    {
        float* As = smem;
        float* Bs = smem + TILE_FLOATS;
        float4 ar[4];
#pragma unroll
        for (int i = 0; i < 4; i++) ar[i] = *(const float4*)(aptr[i]);
#pragma unroll
        for (int i = 0; i < 4; i++)
            CP_ASYNC16(smem_u32(Bs + (r0 + 32*i) * KPAD36 + q * 4), bptr[i]);
        CP_COMMIT();
#pragma unroll
        for (int i = 0; i < 4; i++) {
            float4 t;
            t.x = to_tf32(ar[i].x); t.y = to_tf32(ar[i].y);
            t.z = to_tf32(ar[i].z); t.w = to_tf32(ar[i].w);
            *(float4*)(As + (r0 + 32*i) * KPAD36 + q * 4) = t;
        }
        CP_WAIT0();
        __syncthreads();
    }

    for (int it = 0; it < nIter; it++) {
        int s = it & 1, ns = s ^ 1;
        bool more = (it + 1 < nIter);
        float* As  = smem + s  * STAGE_FLOATS;
        float* Bs  = As + TILE_FLOATS;
        float* Asn = smem + ns * STAGE_FLOATS;
        float* Bsn = Asn + TILE_FLOATS;

        float4 ar[4];
        if (more) {
            int k0 = (it + 1) * 32;
#pragma unroll
            for (int i = 0; i < 4; i++) ar[i] = *(const float4*)(aptr[i] + k0);
#pragma unroll
            for (int i = 0; i < 4; i++)
                CP_ASYNC16(smem_u32(Bsn + (r0 + 32*i) * KPAD36 + q * 4), bptr[i] + k0);
            CP_COMMIT();
        }

        const float* Aw = As + (warpM * 64 + gr) * KPAD36 + gc;
        const float* Bw = Bs + (warpN * 32 + gr) * KPAD36 + gc;
#pragma unroll
        for (int ks = 0; ks < 4; ks++) {
            uint32_t af[4][4];
            uint32_t bf[4][2];
#pragma unroll
            for (int mf = 0; mf < 4; mf++) {
                const float* p = Aw + mf * 16 * KPAD36 + ks * 8;
                af[mf][0] = __float_as_uint(p[0]);
                af[mf][1] = __float_as_uint(p[8 * KPAD36]);
                af[mf][2] = __float_as_uint(p[4]);
                af[mf][3] = __float_as_uint(p[8 * KPAD36 + 4]);
            }
#pragma unroll
            for (int nf = 0; nf < 4; nf++) {
                const float* p = Bw + nf * 8 * KPAD36 + ks * 8;
                bf[nf][0] = __float_as_uint(p[0]);
                bf[nf][1] = __float_as_uint(p[4]);
            }
#pragma unroll
            for (int mf = 0; mf < 4; mf++)
#pragma unroll
                for (int nf = 0; nf < 4; nf++)
                    mma_tf32(acc[mf][nf], af[mf], bf[nf]);
        }

        if (more) {
#pragma unroll
            for (int i = 0; i < 4; i++) {
                float4 t;
                t.x = to_tf32(ar[i].x); t.y = to_tf32(ar[i].y);
                t.z = to_tf32(ar[i].z); t.w = to_tf32(ar[i].w);
                *(float4*)(Asn + (r0 + 32*i) * KPAD36 + q * 4) = t;
            }
            CP_WAIT0();
        }
        __syncthreads();
    }

#pragma unroll
    for (int mf = 0; mf < 4; mf++) {
#pragma unroll
        for (int half = 0; half < 2; half++) {
            int m = rowBase + warpM * 64 + mf * 16 + gr + half * 8;
            if (m >= Meff) continue;
            if (MODE == 3) {
                int trow = scatterIdx[m];
                float wgt = scatterW[m];
                float* crow = C + (size_t)trow * N;
#pragma unroll
                for (int nf = 0; nf < 4; nf++) {
                    int col = colBase + warpN * 32 + nf * 8 + gc * 2;
                    float v0 = acc[mf][nf][half*2+0] + bias[col];
                    float v1 = acc[mf][nf][half*2+1] + bias[col+1];
                    crow[col]   += wgt * v0;
                    crow[col+1] += wgt * v1;
                }
            } else {
                float* crow = C + (size_t)m * N;
                const float* rrow = (MODE == 1) ? (res + (size_t)m * N) : nullptr;
#pragma unroll
                for (int nf = 0; nf < 4; nf++) {
                    int col = colBase + warpN * 32 + nf * 8 + gc * 2;
                    float v0 = acc[mf][nf][half*2+0] + bias[col];
                    float v1 = acc[mf][nf][half*2+1] + bias[col+1];
                    if (MODE == 1) { v0 += rrow[col]; v1 += rrow[col+1]; }
                    if (MODE == 2) { v0 = gelu_exact(v0); v1 = gelu_exact(v1); }
                    if (MODE == 4) { v0 = to_tf32(v0); v1 = to_tf32(v1); }
                    crow[col]   = v0;
                    crow[col+1] = v1;
                }
            }
        }
    }
}

// ---------------- MoE gate + routing ----------------
__global__ __launch_bounds__(128) void gate_route_kernel(
    const float* __restrict__ xn, const float* __restrict__ wg)
{
    int trow = blockIdx.x;
    const float* xr = xn + (size_t)trow * DD;
    float p[4] = {0.f, 0.f, 0.f, 0.f};
    for (int d = threadIdx.x; d < DD; d += 128) {
        float xv = xr[d];
#pragma unroll
        for (int e = 0; e < 4; e++) p[e] += xv * wg[d*4 + e];
    }
    __shared__ float red[4][128];
#pragma unroll
    for (int e = 0; e < 4; e++) red[e][threadIdx.x] = p[e];
    __syncthreads();
    for (int st = 64; st > 0; st >>= 1) {
        if (threadIdx.x < st)
#pragma unroll
            for (int e = 0; e < 4; e++) red[e][threadIdx.x] += red[e][threadIdx.x + st];
        __syncthreads();
    }
    if (threadIdx.x == 0) {
        float lg[4];
#pragma unroll
        for (int e = 0; e < 4; e++) lg[e] = red[e][0];
        float mx = fmaxf(fmaxf(lg[0], lg[1]), fmaxf(lg[2], lg[3]));
        float ex[4], ssum = 0.f;
#pragma unroll
        for (int e = 0; e < 4; e++) { ex[e] = expf(lg[e] - mx); ssum += ex[e]; }
        float pr[4];
#pragma unroll
        for (int e = 0; e < 4; e++) pr[e] = ex[e] / ssum;
        int i0 = 0;
        for (int e = 1; e < 4; e++) if (pr[e] > pr[i0]) i0 = e;
        int i1 = -1;
        for (int e = 0; e < 4; e++) if (e != i0 && (i1 < 0 || pr[e] > pr[i1])) i1 = e;
        float e1 = expf(pr[i1] - pr[i0]);
        float w0 = 1.f / (1.f + e1);
        float w1 = e1 / (1.f + e1);
        int s0 = atomicAdd(&g_cnt[i0], 1);
        g_tok[i0*TT + s0] = trow; g_w[i0*TT + s0] = w0;
        int s1 = atomicAdd(&g_cnt[i1], 1);
        g_tok[i1*TT + s1] = trow; g_w[i1*TT + s1] = w1;
    }
}

// ---------------- launch ----------------
extern "C" void kernel_launch(void* const* d_in, const int* in_sizes, int n_in,
                              void* d_out, int out_size) {
    const float* x    = (const float*)d_in[0];
    const float* wq   = (const float*)d_in[1];
    const float* bq   = (const float*)d_in[2];
    const float* wk   = (const float*)d_in[3];
    const float* bk   = (const float*)d_in[4];
    const float* wv   = (const float*)d_in[5];
    const float* bv   = (const float*)d_in[6];
    const float* wo   = (const float*)d_in[7];
    const float* bo   = (const float*)d_in[8];
    const float* ln1w = (const float*)d_in[9];
    const float* ln1b = (const float*)d_in[10];
    const float* ln2w = (const float*)d_in[11];
    const float* ln2b = (const float*)d_in[12];
    const float* wg   = (const float*)d_in[13];
    const float* we1  = (const float*)d_in[14];
    const float* be1  = (const float*)d_in[15];
    const float* we2  = (const float*)d_in[16];
    const float* be2  = (const float*)d_in[17];
    float* out = (float*)d_out;

    float *xn, *q, *k, *v, *attn, *h, *hmid, *tw;
    float *wqt, *wkt, *wvt, *wot, *we1t, *we2t;
    int *cnt, *tok;
    cudaGetSymbolAddress((void**)&xn,   g_xn);
    cudaGetSymbolAddress((void**)&q,    g_q);
    cudaGetSymbolAddress((void**)&k,    g_k);
    cudaGetSymbolAddress((void**)&v,    g_v);
    cudaGetSymbolAddress((void**)&attn, g_attn);
    cudaGetSymbolAddress((void**)&h,    g_h);
    cudaGetSymbolAddress((void**)&hmid, g_hmid);
    cudaGetSymbolAddress((void**)&cnt,  g_cnt);
    cudaGetSymbolAddress((void**)&tok,  g_tok);
    cudaGetSymbolAddress((void**)&tw,   g_w);
    cudaGetSymbolAddress((void**)&wqt,  g_wqt);
    cudaGetSymbolAddress((void**)&wkt,  g_wkt);
    cudaGetSymbolAddress((void**)&wvt,  g_wvt);
    cudaGetSymbolAddress((void**)&wot,  g_wot);
    cudaGetSymbolAddress((void**)&we1t, g_we1t);
    cudaGetSymbolAddress((void**)&we2t, g_we2t);

    cudaFuncSetAttribute(mma_gemm_kernel<0, false>, cudaFuncAttributeMaxDynamicSharedMemorySize, GEMM_SMEM_BYTES);
    cudaFuncSetAttribute(mma_gemm_kernel<1, false>, cudaFuncAttributeMaxDynamicSharedMemorySize, GEMM_SMEM_BYTES);
    cudaFuncSetAttribute(mma_gemm_kernel<2, true >, cudaFuncAttributeMaxDynamicSharedMemorySize, GEMM_SMEM_BYTES);
    cudaFuncSetAttribute(mma_gemm_kernel<3, false>, cudaFuncAttributeMaxDynamicSharedMemorySize, GEMM_SMEM_BYTES);
    cudaFuncSetAttribute(mma_gemm_kernel<4, false>, cudaFuncAttributeMaxDynamicSharedMemorySize, GEMM_SMEM_BYTES);
    cudaFuncSetAttribute(flash_mma_kernel, cudaFuncAttributeMaxDynamicSharedMemorySize, FLASH_SMEM);

    zero_cnt_kernel<<<1, 32>>>();

    // transpose + tf32-round all weights into [N,K]
    dim3 tg(DD / 32, DD / 32);
    transpose_tf32_kernel<<<tg, 256>>>(wq, wqt);
    transpose_tf32_kernel<<<tg, 256>>>(wk, wkt);
    transpose_tf32_kernel<<<tg, 256>>>(wv, wvt);
    transpose_tf32_kernel<<<tg, 256>>>(wo, wot);
    for (int e = 0; e < EE; e++) {
        transpose_tf32_kernel<<<tg, 256>>>(we1 + (size_t)e * DD * II, we1t + (size_t)e * II * DD);
        transpose_tf32_kernel<<<tg, 256>>>(we2 + (size_t)e * II * DD, we2t + (size_t)e * DD * II);
    }

    // LN1
    layernorm_kernel<<<TT, 256>>>(x, ln1w, ln1b, xn);

    // QKV projections (V rounded to tf32 for flash)
    dim3 gg(DD / 128, TT / 128);
    mma_gemm_kernel<0, false><<<gg, 256, GEMM_SMEM_BYTES>>>(xn, wqt, bq, q, nullptr, nullptr, nullptr, nullptr, nullptr, TT, DD, DD);
    mma_gemm_kernel<0, false><<<gg, 256, GEMM_SMEM_BYTES>>>(xn, wkt, bk, k, nullptr, nullptr, nullptr, nullptr, nullptr, TT, DD, DD);
    mma_gemm_kernel<4, false><<<gg, 256, GEMM_SMEM_BYTES>>>(xn, wvt, bv, v, nullptr, nullptr, nullptr, nullptr, nullptr, TT, DD, DD);

    // RoPE (rounds Q,K to tf32)
    rope_kernel<<<(TT * HH * 64) / 256, 256>>>(q, k);

    // tensor-core causal flash attention
    flash_mma_kernel<<<dim3(SS / FQT, BB * HH), 256, FLASH_SMEM>>>(q, k, v, attn);

    // O projection + residual -> h
    mma_gemm_kernel<1, false><<<gg, 256, GEMM_SMEM_BYTES>>>(attn, wot, bo, h, x, nullptr, nullptr, nullptr, nullptr, TT, DD, DD);

    // out = h (MoE accumulates on top)
    copy_kernel<<<(TT * DD / 4 + 255) / 256, 256>>>((const float4*)h, (float4*)out, TT * DD / 4);

    // LN2
    layernorm_kernel<<<TT, 256>>>(h, ln2w, ln2b, xn);

    // gate + routing
    gate_route_kernel<<<TT, 128>>>(xn, wg);

    // experts
    for (int e = 0; e < EE; e++) {
        mma_gemm_kernel<2, true><<<dim3(II / 128, TT / 128), 256, GEMM_SMEM_BYTES>>>(
            xn, we1t + (size_t)e * II * DD, be1 + (size_t)e * II, hmid,
            nullptr, tok + e * TT, cnt + e, nullptr, nullptr, TT, II, DD);
        mma_gemm_kernel<3, false><<<dim3(DD / 128, TT / 128), 256, GEMM_SMEM_BYTES>>>(
            hmid, we2t + (size_t)e * DD * II, be2 + (size_t)e * DD, out,
            nullptr, nullptr, cnt + e, tok + e * TT, tw + e * TT, TT, DD, II);
    }
}